// round 1
// baseline (speedup 1.0000x reference)
#include <cuda_runtime.h>
#include <math.h>

#define B_    2048
#define K_    20
#define TK_   40
#define D_    128
#define T_    100
#define C_    128
#define HT_   20
#define HC_   512
#define F1_   228   /* D+T  */
#define F2_   484   /* 3D+T */

#define TR_   32
#define XS_   132
#define HS_   516
#define WS_   132

// ---------------- scratch (no allocations allowed) ----------------
__device__ float g_tok1[B_ * TK_ * C_];
__device__ float g_tok2[B_ * TK_ * C_];

__device__ __forceinline__ float gelu_f(float x) {
    return 0.5f * x * (1.0f + erff(x * 0.70710678118654752f));
}

// ---------------- one-hop token build: gather + time-enc + proj ----------------
__global__ __launch_bounds__(128)
void k_build1(const float* __restrict__ et, const int* __restrict__ se,
              const int* __restrict__ de, const float* __restrict__ dts,
              const float* __restrict__ dtd, const float* __restrict__ tw,
              const float* __restrict__ tb, const float* __restrict__ pW,
              const float* __restrict__ pb, float* __restrict__ out)
{
    __shared__ float feat[TK_ * F1_];
    __shared__ int   s_eid[TK_];
    __shared__ float s_dt[TK_];
    int b = blockIdx.x, tid = threadIdx.x;
    if (tid < TK_) {
        int half = tid / K_, k = tid - half * K_;
        int eid = half ? de[b * K_ + k] : se[b * K_ + k];
        s_eid[tid] = eid;
        s_dt[tid]  = half ? dtd[b * K_ + k] : dts[b * K_ + k];
    }
    __syncthreads();
    for (int idx = tid; idx < TK_ * F1_; idx += 128) {
        int t = idx / F1_, f = idx - t * F1_;
        float v;
        if (f < D_) {
            v = et[(long)s_eid[t] * D_ + f];
        } else {
            int j = f - D_;
            v = (s_eid[t] == 0) ? 0.0f : cosf(s_dt[t] * tw[j] + tb[j]);
        }
        feat[idx] = v;
    }
    __syncthreads();
    float acc[TK_];
#pragma unroll
    for (int t = 0; t < TK_; t++) acc[t] = 0.0f;
    int c = tid;
    for (int k = 0; k < F1_; k++) {
        float w = pW[k * C_ + c];
#pragma unroll
        for (int t = 0; t < TK_; t++) acc[t] += feat[t * F1_ + k] * w;
    }
    float bias = pb[c];
    float* ob = out + (long)b * TK_ * C_ + c;
#pragma unroll
    for (int t = 0; t < TK_; t++) ob[t * C_] = acc[t] + bias;
}

// ---------------- two-hop token build ----------------
__global__ __launch_bounds__(128)
void k_build2(const float* __restrict__ et, const int* __restrict__ se,
              const int* __restrict__ de, const int* __restrict__ s2a,
              const int* __restrict__ s2b, const int* __restrict__ d2a,
              const int* __restrict__ d2b, const float* __restrict__ dt2s,
              const float* __restrict__ dt2d, const float* __restrict__ tw,
              const float* __restrict__ tb, const float* __restrict__ eW,
              const float* __restrict__ eb, float* __restrict__ out)
{
    __shared__ float feat[K_ * F2_];
    __shared__ int s1[K_], s2[K_], s3[K_];
    __shared__ float sdt[K_];
    int bh = blockIdx.x;
    int b = bh >> 1, half = bh & 1, tid = threadIdx.x;
    if (tid < K_) {
        s1[tid] = half ? d2a[b * K_ + tid] : s2a[b * K_ + tid];
        s2[tid] = half ? d2b[b * K_ + tid] : s2b[b * K_ + tid];
        s3[tid] = half ? de[b * K_ + tid]  : se[b * K_ + tid];
        sdt[tid] = half ? dt2d[b * K_ + tid] : dt2s[b * K_ + tid];
    }
    __syncthreads();
    for (int idx = tid; idx < K_ * F2_; idx += 128) {
        int t = idx / F2_, f = idx - t * F2_;
        float v;
        if (f < D_)              v = et[(long)s1[t] * D_ + f];
        else if (f < 2 * D_)     v = et[(long)s2[t] * D_ + (f - D_)];
        else if (f < 3 * D_)     v = et[(long)s3[t] * D_ + (f - 2 * D_)];
        else {
            int j = f - 3 * D_;
            v = (s1[t] == 0) ? 0.0f : cosf(sdt[t] * tw[j] + tb[j]);
        }
        feat[idx] = v;
    }
    __syncthreads();
    const float* W = eW + (long)half * F2_ * C_;
    float acc[K_];
#pragma unroll
    for (int t = 0; t < K_; t++) acc[t] = 0.0f;
    int c = tid;
    for (int k = 0; k < F2_; k++) {
        float w = W[k * C_ + c];
#pragma unroll
        for (int t = 0; t < K_; t++) acc[t] += feat[t * F2_ + k] * w;
    }
    float bias = eb[half * C_ + c];
    float* ob = out + ((long)b * TK_ + half * K_) * C_ + c;
#pragma unroll
    for (int t = 0; t < K_; t++) ob[t * C_] = acc[t] + bias;
}

// ---------------- token mixing: LN over token axis + FFN 40->20->40 ----------------
__global__ __launch_bounds__(128)
void k_tokmix(float* __restrict__ x, const float* __restrict__ tg,
              const float* __restrict__ tbb, const float* __restrict__ W1,
              const float* __restrict__ b1, const float* __restrict__ W2,
              const float* __restrict__ b2, int mi)
{
    __shared__ float sW1[TK_ * HT_], sW2[HT_ * TK_];
    __shared__ float sb1[HT_], sb2[TK_], sg[TK_], sb[TK_];
    int tid = threadIdx.x, b = blockIdx.x;
    for (int i = tid; i < TK_ * HT_; i += 128) sW1[i] = W1[mi * TK_ * HT_ + i];
    for (int i = tid; i < HT_ * TK_; i += 128) sW2[i] = W2[mi * HT_ * TK_ + i];
    if (tid < HT_) sb1[tid] = b1[mi * HT_ + tid];
    if (tid < TK_) {
        sb2[tid] = b2[mi * TK_ + tid];
        sg[tid]  = tg[mi * TK_ + tid];
        sb[tid]  = tbb[mi * TK_ + tid];
    }
    __syncthreads();

    float* xb = x + (long)b * TK_ * C_ + tid;
    float xv[TK_];
#pragma unroll
    for (int t = 0; t < TK_; t++) xv[t] = xb[t * C_];
    float m = 0.0f;
#pragma unroll
    for (int t = 0; t < TK_; t++) m += xv[t];
    m *= (1.0f / TK_);
    float var = 0.0f;
#pragma unroll
    for (int t = 0; t < TK_; t++) { float d = xv[t] - m; var += d * d; }
    var *= (1.0f / TK_);
    float inv = rsqrtf(var + 1e-5f);
    float xn[TK_];
#pragma unroll
    for (int t = 0; t < TK_; t++) xn[t] = (xv[t] - m) * inv * sg[t] + sb[t];
    float g[HT_];
#pragma unroll
    for (int j = 0; j < HT_; j++) {
        float s = sb1[j];
#pragma unroll
        for (int t = 0; t < TK_; t++) s += xn[t] * sW1[t * HT_ + j];
        g[j] = gelu_f(s);
    }
#pragma unroll
    for (int t = 0; t < TK_; t++) {
        float o = sb2[t];
#pragma unroll
        for (int j = 0; j < HT_; j++) o += g[j] * sW2[j * TK_ + t];
        xb[t * C_] = xv[t] + o;
    }
}

// ---------------- channel mixing: LN over C + FFN 128->512->128 (fused) ----------------
__global__ __launch_bounds__(256)
void k_chmix(float* __restrict__ X, const float* __restrict__ cg,
             const float* __restrict__ cb, const float* __restrict__ W1,
             const float* __restrict__ b1, const float* __restrict__ W2,
             const float* __restrict__ b2, int mi)
{
    extern __shared__ float sm[];
    float* xn = sm;                      // TR_ * XS_
    float* hs = xn + TR_ * XS_;          // TR_ * HS_
    float* ws = hs + TR_ * HS_;          // 128 * WS_
    __shared__ float scg[C_], scb[C_], sbb1[HC_], sbb2[C_];
    int tid = threadIdx.x;
    for (int i = tid; i < C_; i += 256) {
        scg[i]  = cg[mi * C_ + i];
        scb[i]  = cb[mi * C_ + i];
        sbb2[i] = b2[mi * C_ + i];
    }
    for (int i = tid; i < HC_; i += 256) sbb1[i] = b1[mi * HC_ + i];
    __syncthreads();

    long row0 = (long)blockIdx.x * TR_;
    int warp = tid >> 5, lane = tid & 31;

    // LayerNorm over C for 32 rows (4 rows per warp)
    for (int rr = 0; rr < 4; rr++) {
        int r = warp * 4 + rr;
        const float* xr = X + (row0 + r) * C_;
        float v0 = xr[lane], v1 = xr[lane + 32], v2 = xr[lane + 64], v3 = xr[lane + 96];
        float s = v0 + v1 + v2 + v3;
        for (int o = 16; o; o >>= 1) s += __shfl_xor_sync(0xffffffffu, s, o);
        float m = s * (1.0f / C_);
        float d0 = v0 - m, d1 = v1 - m, d2 = v2 - m, d3 = v3 - m;
        float q = d0 * d0 + d1 * d1 + d2 * d2 + d3 * d3;
        for (int o = 16; o; o >>= 1) q += __shfl_xor_sync(0xffffffffu, q, o);
        float inv = rsqrtf(q * (1.0f / C_) + 1e-5f);
        float* xo = xn + r * XS_;
        xo[lane]      = d0 * inv * scg[lane]      + scb[lane];
        xo[lane + 32] = d1 * inv * scg[lane + 32] + scb[lane + 32];
        xo[lane + 64] = d2 * inv * scg[lane + 64] + scb[lane + 64];
        xo[lane + 96] = d3 * inv * scg[lane + 96] + scb[lane + 96];
    }

    const float* W1p = W1 + (long)mi * C_ * HC_;
    const float* W2p = W2 + (long)mi * HC_ * C_;
    int rt = tid >> 5, ct = tid & 31;

    // GEMM1: h[32][512] = gelu(xn @ W1 + b1), staged 128 cols at a time
    for (int nb = 0; nb < 4; nb++) {
        __syncthreads();
        for (int idx = tid; idx < 128 * 32; idx += 256) {
            int k = idx >> 5, j4 = idx & 31;
            float4 w = *(const float4*)(W1p + k * HC_ + nb * 128 + j4 * 4);
            *(float4*)(ws + k * WS_ + j4 * 4) = w;
        }
        __syncthreads();
        float acc[4][4];
#pragma unroll
        for (int a = 0; a < 4; a++)
#pragma unroll
            for (int q = 0; q < 4; q++) acc[a][q] = 0.0f;
#pragma unroll 4
        for (int k = 0; k < 128; k++) {
            float4 wv = *(const float4*)(ws + k * WS_ + ct * 4);
            float x0 = xn[(rt * 4 + 0) * XS_ + k];
            float x1 = xn[(rt * 4 + 1) * XS_ + k];
            float x2 = xn[(rt * 4 + 2) * XS_ + k];
            float x3 = xn[(rt * 4 + 3) * XS_ + k];
            acc[0][0] += x0 * wv.x; acc[0][1] += x0 * wv.y; acc[0][2] += x0 * wv.z; acc[0][3] += x0 * wv.w;
            acc[1][0] += x1 * wv.x; acc[1][1] += x1 * wv.y; acc[1][2] += x1 * wv.z; acc[1][3] += x1 * wv.w;
            acc[2][0] += x2 * wv.x; acc[2][1] += x2 * wv.y; acc[2][2] += x2 * wv.z; acc[2][3] += x2 * wv.w;
            acc[3][0] += x3 * wv.x; acc[3][1] += x3 * wv.y; acc[3][2] += x3 * wv.z; acc[3][3] += x3 * wv.w;
        }
#pragma unroll
        for (int rr = 0; rr < 4; rr++) {
            float* hp = hs + (rt * 4 + rr) * HS_ + nb * 128 + ct * 4;
#pragma unroll
            for (int q = 0; q < 4; q++)
                hp[q] = gelu_f(acc[rr][q] + sbb1[nb * 128 + ct * 4 + q]);
        }
    }

    // GEMM2: y[32][128] = h @ W2, K staged 128 at a time
    float a2[4][4];
#pragma unroll
    for (int a = 0; a < 4; a++)
#pragma unroll
        for (int q = 0; q < 4; q++) a2[a][q] = 0.0f;
    for (int kb = 0; kb < 4; kb++) {
        __syncthreads();
        for (int idx = tid; idx < 128 * 32; idx += 256) {
            int k = idx >> 5, j4 = idx & 31;
            float4 w = *(const float4*)(W2p + (long)(kb * 128 + k) * C_ + j4 * 4);
            *(float4*)(ws + k * WS_ + j4 * 4) = w;
        }
        __syncthreads();
#pragma unroll 4
        for (int k = 0; k < 128; k++) {
            float4 wv = *(const float4*)(ws + k * WS_ + ct * 4);
            float h0 = hs[(rt * 4 + 0) * HS_ + kb * 128 + k];
            float h1 = hs[(rt * 4 + 1) * HS_ + kb * 128 + k];
            float h2 = hs[(rt * 4 + 2) * HS_ + kb * 128 + k];
            float h3 = hs[(rt * 4 + 3) * HS_ + kb * 128 + k];
            a2[0][0] += h0 * wv.x; a2[0][1] += h0 * wv.y; a2[0][2] += h0 * wv.z; a2[0][3] += h0 * wv.w;
            a2[1][0] += h1 * wv.x; a2[1][1] += h1 * wv.y; a2[1][2] += h1 * wv.z; a2[1][3] += h1 * wv.w;
            a2[2][0] += h2 * wv.x; a2[2][1] += h2 * wv.y; a2[2][2] += h2 * wv.z; a2[2][3] += h2 * wv.w;
            a2[3][0] += h3 * wv.x; a2[3][1] += h3 * wv.y; a2[3][2] += h3 * wv.z; a2[3][3] += h3 * wv.w;
        }
    }

    // residual + bias, in place
#pragma unroll
    for (int rr = 0; rr < 4; rr++) {
        long row = row0 + rt * 4 + rr;
        float4 xv = *(const float4*)(X + row * C_ + ct * 4);
        float4 o;
        o.x = xv.x + a2[rr][0] + sbb2[ct * 4 + 0];
        o.y = xv.y + a2[rr][1] + sbb2[ct * 4 + 1];
        o.z = xv.z + a2[rr][2] + sbb2[ct * 4 + 2];
        o.w = xv.w + a2[rr][3] + sbb2[ct * 4 + 3];
        *(float4*)(X + row * C_ + ct * 4) = o;
    }
}

// ---------------- mean over tokens + pcc-softmax combine ----------------
__global__ __launch_bounds__(128)
void k_final(const float* __restrict__ t1, const float* __restrict__ t2,
             const float* __restrict__ pcc1, const float* __restrict__ pcc2,
             float* __restrict__ out)
{
    int b = blockIdx.x, c = threadIdx.x;
    const float* p1 = t1 + (long)b * TK_ * C_ + c;
    const float* p2 = t2 + (long)b * TK_ * C_ + c;
    float s1 = 0.0f, s2 = 0.0f;
#pragma unroll
    for (int t = 0; t < TK_; t++) { s1 += p1[t * C_]; s2 += p2[t * C_]; }
    s1 *= (1.0f / TK_);
    s2 *= (1.0f / TK_);
    float a = pcc1[b], bb = pcc2[b];
    float m = fmaxf(a, bb);
    float e1 = expf(a - m), e2 = expf(bb - m);
    float w1 = e1 / (e1 + e2);
    out[(long)b * C_ + c] = w1 * s1 + (1.0f - w1) * s2;
}

// ---------------- launch ----------------
extern "C" void kernel_launch(void* const* d_in, const int* in_sizes, int n_in,
                              void* d_out, int out_size)
{
    const float* edge_table = (const float*)d_in[0];
    const int*   src_eids   = (const int*)d_in[1];
    const int*   dst_eids   = (const int*)d_in[2];
    const int*   src2_e1    = (const int*)d_in[3];
    const int*   src2_e2    = (const int*)d_in[4];
    const int*   dst2_e1    = (const int*)d_in[5];
    const int*   dst2_e2    = (const int*)d_in[6];
    const float* dt_src     = (const float*)d_in[7];
    const float* dt_dst     = (const float*)d_in[8];
    const float* dt2_src    = (const float*)d_in[9];
    const float* dt2_dst    = (const float*)d_in[10];
    const float* pcc1       = (const float*)d_in[11];
    const float* pcc2       = (const float*)d_in[12];
    const float* time_w     = (const float*)d_in[13];
    const float* time_b     = (const float*)d_in[14];
    const float* proj_W     = (const float*)d_in[15];
    const float* proj_b     = (const float*)d_in[16];
    const float* eproj_W    = (const float*)d_in[17];
    const float* eproj_b    = (const float*)d_in[18];
    const float* tln_g      = (const float*)d_in[19];
    const float* tln_b      = (const float*)d_in[20];
    const float* tW1        = (const float*)d_in[21];
    const float* tb1        = (const float*)d_in[22];
    const float* tW2        = (const float*)d_in[23];
    const float* tb2        = (const float*)d_in[24];
    const float* cln_g      = (const float*)d_in[25];
    const float* cln_b      = (const float*)d_in[26];
    const float* cW1        = (const float*)d_in[27];
    const float* cb1        = (const float*)d_in[28];
    const float* cW2        = (const float*)d_in[29];
    const float* cb2        = (const float*)d_in[30];
    float* out = (float*)d_out;

    float* tok1; cudaGetSymbolAddress((void**)&tok1, g_tok1);
    float* tok2; cudaGetSymbolAddress((void**)&tok2, g_tok2);

    const int smem_ch = (TR_ * XS_ + TR_ * HS_ + 128 * WS_) * (int)sizeof(float);
    cudaFuncSetAttribute(k_chmix, cudaFuncAttributeMaxDynamicSharedMemorySize, smem_ch);

    // ---- stack 1: one-hop ----
    k_build1<<<B_, 128>>>(edge_table, src_eids, dst_eids, dt_src, dt_dst,
                          time_w, time_b, proj_W, proj_b, tok1);
    for (int i = 0; i < 2; i++) {
        k_tokmix<<<B_, 128>>>(tok1, tln_g, tln_b, tW1, tb1, tW2, tb2, i);
        k_chmix<<<(B_ * TK_) / TR_, 256, smem_ch>>>(tok1, cln_g, cln_b,
                                                    cW1, cb1, cW2, cb2, i);
    }

    // ---- stack 2: two-hop ----
    k_build2<<<2 * B_, 128>>>(edge_table, src_eids, dst_eids,
                              src2_e1, src2_e2, dst2_e1, dst2_e2,
                              dt2_src, dt2_dst, time_w, time_b,
                              eproj_W, eproj_b, tok2);
    for (int i = 0; i < 2; i++) {
        k_tokmix<<<B_, 128>>>(tok2, tln_g, tln_b, tW1, tb1, tW2, tb2, 2 + i);
        k_chmix<<<(B_ * TK_) / TR_, 256, smem_ch>>>(tok2, cln_g, cln_b,
                                                    cW1, cb1, cW2, cb2, 2 + i);
    }

    k_final<<<B_, 128>>>(tok1, tok2, pcc1, pcc2, out);
}